// round 14
// baseline (speedup 1.0000x reference)
#include <cuda_runtime.h>
#include <cuda_bf16.h>
#include <cstdint>

#define B_ 4
#define S_ 2048
#define E_ 1024
#define A_ 128
#define M_ (B_*S_)   // 8192

// ---- mma.sync bf16 + ldmatrix (base ISA, compiles for compute_103) ----
__device__ __forceinline__ void mma16816(float* d, const unsigned* a, const unsigned* b) {
    asm volatile(
        "mma.sync.aligned.m16n8k16.row.col.f32.bf16.bf16.f32 "
        "{%0,%1,%2,%3}, {%4,%5,%6,%7}, {%8,%9}, {%0,%1,%2,%3};"
        : "+f"(d[0]), "+f"(d[1]), "+f"(d[2]), "+f"(d[3])
        : "r"(a[0]), "r"(a[1]), "r"(a[2]), "r"(a[3]), "r"(b[0]), "r"(b[1]));
}
__device__ __forceinline__ void ldm_x4(unsigned* r, uint32_t addr) {
    asm volatile("ldmatrix.sync.aligned.m8n8.x4.shared.b16 {%0,%1,%2,%3}, [%4];"
        : "=r"(r[0]), "=r"(r[1]), "=r"(r[2]), "=r"(r[3]) : "r"(addr));
}
__device__ __forceinline__ uint32_t smem_u32(const void* p) {
    uint32_t a;
    asm("{ .reg .u64 t; cvta.to.shared.u64 t, %1; cvt.u32.u64 %0, t; }"
        : "=r"(a) : "l"(p));
    return a;
}

__device__ __forceinline__ unsigned pack_bf16_hi(float a, float b) {
    __nv_bfloat162 h = __floats2bfloat162_rn(a, b);
    return *reinterpret_cast<unsigned*>(&h);
}
__device__ __forceinline__ unsigned pack_bf16_lo(float a, float b) {
    float ra = a - __bfloat162float(__float2bfloat16(a));
    float rb = b - __bfloat162float(__float2bfloat16(b));
    __nv_bfloat162 h = __floats2bfloat162_rn(ra, rb);
    return *reinterpret_cast<unsigned*>(&h);
}

// scratch (device globals: no allocation allowed)
__device__ __nv_bfloat16 g_xhi[M_*E_], g_xlo[M_*E_];
__device__ __nv_bfloat16 g_whi[3*A_*E_], g_wlo[3*A_*E_];
__device__ __nv_bfloat16 g_qhi[M_*A_], g_qlo[M_*A_];
__device__ __nv_bfloat16 g_khi[M_*A_], g_klo[M_*A_];
__device__ __nv_bfloat16 g_vthi[M_*A_], g_vtlo[M_*A_];
__device__ float  g_po [4*32*4*64*128];
__device__ float2 g_pml[4*32*4*64];

// ---------------------------------------------------------------------------
// split_xw (R12-proven, unchanged)
// ---------------------------------------------------------------------------
__global__ __launch_bounds__(256) void split_xw(
    const float* __restrict__ x,
    const float* __restrict__ Wk,
    const float* __restrict__ Wq,
    const float* __restrict__ Wv)
{
    const int NX  = M_ * E_ / 4;
    const int NW1 = A_ * E_ / 4;
    const int NT  = NX + 3 * NW1;
    for (int i = blockIdx.x * blockDim.x + threadIdx.x; i < NT;
         i += gridDim.x * blockDim.x) {
        const float4* src;
        __nv_bfloat16 *dh, *dl;
        int idx;
        if (i < NX) {
            src = (const float4*)x; idx = i; dh = g_xhi; dl = g_xlo;
        } else {
            int j = i - NX; int w = j / NW1; idx = j - w * NW1;
            src = (const float4*)(w == 0 ? Wk : (w == 1 ? Wq : Wv));
            dh = g_whi + (size_t)w * A_ * E_;
            dl = g_wlo + (size_t)w * A_ * E_;
        }
        float4 v = src[idx];
        uint2 h, l;
        h.x = pack_bf16_hi(v.x, v.y); h.y = pack_bf16_hi(v.z, v.w);
        l.x = pack_bf16_lo(v.x, v.y); l.y = pack_bf16_lo(v.z, v.w);
        *(uint2*)(dh + (size_t)idx * 4) = h;
        *(uint2*)(dl + (size_t)idx * 4) = l;
    }
}

// ---------------------------------------------------------------------------
// Projection, bf16 3-split, frag loads via ldmatrix.
// ---------------------------------------------------------------------------
#define PP 36
#define TILE_W (128 * PP)
#define DP 132
#define PROJ_SMEM (4 * TILE_W * 4)

__global__ __launch_bounds__(256, 2) void proj_mma2()
{
    extern __shared__ unsigned smu[];
    unsigned* x_hi = smu;
    unsigned* x_lo = smu + TILE_W;
    unsigned* w_hi = smu + 2 * TILE_W;
    unsigned* w_lo = smu + 3 * TILE_W;

    const int which = blockIdx.y;
    const int m0   = blockIdx.x * 128;
    const int tid  = threadIdx.x;
    const int wid  = tid >> 5;
    const int lane = tid & 31;
    const int wr   = wid >> 1;
    const int wc   = wid & 1;
    const int g    = lane >> 2;
    const int t    = lane & 3;
    const int l7   = lane & 7;
    const int lh8  = (lane >> 3) & 1;
    const int lk4  = (lane >> 4) * 4;

    const __nv_bfloat16* wbh = g_whi + (size_t)which * A_ * E_;
    const __nv_bfloat16* wbl = g_wlo + (size_t)which * A_ * E_;

    // ldmatrix lane bases
    const uint32_t aoff = (uint32_t)(((wr * 32 + l7 + lh8 * 8) * PP + lk4) << 2);
    const uint32_t xh_a = smem_u32(x_hi) + aoff;
    const uint32_t xl_a = smem_u32(x_lo) + aoff;
    const uint32_t boff = (uint32_t)(((wc * 64 + l7 + lh8 * 8) * PP + lk4) << 2);
    const uint32_t wh_b = smem_u32(w_hi) + boff;
    const uint32_t wl_b = smem_u32(w_lo) + boff;

    float acc[2][8][4];
#pragma unroll
    for (int rt = 0; rt < 2; rt++)
#pragma unroll
        for (int nt = 0; nt < 8; nt++)
#pragma unroll
            for (int q = 0; q < 4; q++) acc[rt][nt][q] = 0.f;

    const int row  = tid >> 1;
    const int half = tid & 1;

    for (int c = 0; c < 16; c++) {
        __syncthreads();
        {
            const size_t xe = (size_t)(m0 + row) * E_ + c * 64 + half * 32;
            const size_t we = (size_t)row * E_ + c * 64 + half * 32;
            const uint4* sxh = (const uint4*)(g_xhi + xe);
            const uint4* sxl = (const uint4*)(g_xlo + xe);
            const uint4* swh = (const uint4*)(wbh + we);
            const uint4* swl = (const uint4*)(wbl + we);
            const int wb = row * PP + half * 16;
#pragma unroll
            for (int u = 0; u < 4; u++) {
                *(uint4*)&x_hi[wb + 4 * u] = sxh[u];
                *(uint4*)&x_lo[wb + 4 * u] = sxl[u];
                *(uint4*)&w_hi[wb + 4 * u] = swh[u];
                *(uint4*)&w_lo[wb + 4 * u] = swl[u];
            }
        }
        __syncthreads();

#pragma unroll
        for (int ks = 0; ks < 4; ks++) {
            unsigned ah[2][4], al[2][4];
            ldm_x4(ah[0], xh_a + ks * 32);
            ldm_x4(ah[1], xh_a + 16 * PP * 4 + ks * 32);
            ldm_x4(al[0], xl_a + ks * 32);
            ldm_x4(al[1], xl_a + 16 * PP * 4 + ks * 32);
#pragma unroll
            for (int ntp = 0; ntp < 4; ntp++) {
                unsigned b4h[4], b4l[4];
                ldm_x4(b4h, wh_b + ntp * (16 * PP * 4) + ks * 32);
                ldm_x4(b4l, wl_b + ntp * (16 * PP * 4) + ks * 32);
                unsigned bh0[2] = { b4h[0], b4h[2] }, bh1[2] = { b4h[1], b4h[3] };
                unsigned bl0[2] = { b4l[0], b4l[2] }, bl1[2] = { b4l[1], b4l[3] };
#pragma unroll
                for (int rt = 0; rt < 2; rt++) {
                    mma16816(acc[rt][2*ntp],   ah[rt], bh0);
                    mma16816(acc[rt][2*ntp],   ah[rt], bl0);
                    mma16816(acc[rt][2*ntp],   al[rt], bh0);
                    mma16816(acc[rt][2*ntp+1], ah[rt], bh1);
                    mma16816(acc[rt][2*ntp+1], ah[rt], bl1);
                    mma16816(acc[rt][2*ntp+1], al[rt], bh1);
                }
            }
        }
    }

    __syncthreads();
    float* Dsm = (float*)smu;
#pragma unroll
    for (int rt = 0; rt < 2; rt++) {
#pragma unroll
        for (int nt = 0; nt < 8; nt++) {
            const int rowA = wr * 32 + rt * 16 + g;
            const int col  = wc * 64 + nt * 8 + 2 * t;
            *(float2*)&Dsm[rowA * DP + col] =
                make_float2(acc[rt][nt][0], acc[rt][nt][1]);
            *(float2*)&Dsm[(rowA + 8) * DP + col] =
                make_float2(acc[rt][nt][2], acc[rt][nt][3]);
        }
    }
    __syncthreads();

    const int bb = m0 >> 11;
    const int s0 = m0 & (S_ - 1);
    if (which == 2) {
        const int n  = tid >> 1;
        const int r0 = (tid & 1) * 64;
        const size_t base = ((size_t)(bb * A_ + n)) * S_ + s0 + r0;
#pragma unroll
        for (int u = 0; u < 8; u++) {
            float f[8];
#pragma unroll
            for (int j = 0; j < 8; j++) f[j] = Dsm[(r0 + 8 * u + j) * DP + n];
            uint4 h = make_uint4(pack_bf16_hi(f[0], f[1]), pack_bf16_hi(f[2], f[3]),
                                 pack_bf16_hi(f[4], f[5]), pack_bf16_hi(f[6], f[7]));
            uint4 l = make_uint4(pack_bf16_lo(f[0], f[1]), pack_bf16_lo(f[2], f[3]),
                                 pack_bf16_lo(f[4], f[5]), pack_bf16_lo(f[6], f[7]));
            *(uint4*)(g_vthi + base + 8 * u) = h;
            *(uint4*)(g_vtlo + base + 8 * u) = l;
        }
    } else {
        const float sc = (which == 1) ? 0.08838834764831843f : 1.0f;
        __nv_bfloat16* dsth = (which == 1) ? g_qhi : g_khi;
        __nv_bfloat16* dstl = (which == 1) ? g_qlo : g_klo;
        const int rr = tid >> 1;
        const int cb = (tid & 1) * 64;
        const float* sp = &Dsm[rr * DP + cb];
        const size_t base = (size_t)(m0 + rr) * A_ + cb;
#pragma unroll
        for (int u = 0; u < 8; u++) {
            float f[8];
#pragma unroll
            for (int j = 0; j < 8; j++) f[j] = sp[8 * u + j] * sc;
            uint4 h = make_uint4(pack_bf16_hi(f[0], f[1]), pack_bf16_hi(f[2], f[3]),
                                 pack_bf16_hi(f[4], f[5]), pack_bf16_hi(f[6], f[7]));
            uint4 l = make_uint4(pack_bf16_lo(f[0], f[1]), pack_bf16_lo(f[2], f[3]),
                                 pack_bf16_lo(f[4], f[5]), pack_bf16_lo(f[6], f[7]));
            *(uint4*)(dsth + base + 8 * u) = h;
            *(uint4*)(dstl + base + 8 * u) = l;
        }
    }
}

// ---------------------------------------------------------------------------
// Split-K flash attention chunk kernel.
// Key halves now run FULLY INDEPENDENT online softmax (own m,l,O) and merge
// once in the epilogue -> zero softmax barriers in the main loop.
// Frag loads via ldmatrix. 320 CTAs as in R13.
// ---------------------------------------------------------------------------
#define AQP 68
#define AVP 36
#define QW (64 * AQP)
#define VW (128 * AVP)
#define ATTN_SMEM ((4 * QW + 2 * VW) * 4)   // 106496 B

__global__ __launch_bounds__(256) void attn_chunk(float* __restrict__ out)
{
    extern __shared__ unsigned smw[];
    unsigned* qh = smw;
    unsigned* ql = qh + QW;
    unsigned* kh = ql + QW;
    unsigned* kl = kh + QW;
    unsigned* vh = kl + QW;
    unsigned* vl = vh + VW;
    float* obuf = (float*)kh;       // epilogue reuse
    __shared__ float red_m1[4][16];
    __shared__ float red_l1[4][16];

    int cid = blockIdx.x;
    const int b = cid / 80;  cid -= b * 80;
    int qt, chunk;
    if (cid < 8)       { qt = cid;                    chunk = 0; }
    else if (cid < 24) { qt = 8  + ((cid - 8) >> 1);  chunk = (cid - 8) & 1; }
    else if (cid < 48) { qt = 16 + (cid - 24) / 3;    chunk = (cid - 24) % 3; }
    else               { qt = 24 + ((cid - 48) >> 2); chunk = (cid - 48) & 3; }
    const int nch   = (qt >> 3) + 1;
    const int tbase = chunk * 8;
    int ntile = qt + 1 - tbase;
    if (ntile > 8) ntile = 8;
    const int q0 = qt * 64;

    const int tid  = threadIdx.x;
    const int wid  = tid >> 5;
    const int lane = tid & 31;
    const int wr   = wid >> 1;      // row group (16 rows)
    const int wh   = wid & 1;       // key half (32 keys)
    const int g    = lane >> 2;
    const int t    = lane & 3;
    const int l7   = lane & 7;
    const int lh8  = (lane >> 3) & 1;
    const int lk4  = (lane >> 4) * 4;

    // ldmatrix lane bases
    const uint32_t qoff = (uint32_t)(((wr * 16 + l7 + lh8 * 8) * AQP + lk4) << 2);
    const uint32_t qh_a = smem_u32(qh) + qoff;
    const uint32_t ql_a = smem_u32(ql) + qoff;
    const uint32_t koff = (uint32_t)(((wh * 32 + l7 + lh8 * 8) * AQP + lk4) << 2);
    const uint32_t kh_b = smem_u32(kh) + koff;
    const uint32_t kl_b = smem_u32(kl) + koff;
    const uint32_t voff = (uint32_t)((((l7 + lh8 * 8) * AVP) + lk4) << 2);
    const uint32_t vh_b = smem_u32(vh) + voff;
    const uint32_t vl_b = smem_u32(vl) + voff;

    // stage Q tile
    {
        const int row = tid >> 2;
        const int qd  = (tid & 3) * 16;
        const size_t e = (size_t)(b * S_ + q0 + row) * A_ + (tid & 3) * 32;
        const uint4* sh = (const uint4*)(g_qhi + e);
        const uint4* sl = (const uint4*)(g_qlo + e);
        const int wb = row * AQP + qd;
#pragma unroll
        for (int u = 0; u < 4; u++) {
            *(uint4*)&qh[wb + 4 * u] = sh[u];
            *(uint4*)&ql[wb + 4 * u] = sl[u];
        }
    }

    float o[16][4];
#pragma unroll
    for (int nt = 0; nt < 16; nt++)
#pragma unroll
        for (int q = 0; q < 4; q++) o[nt][q] = 0.f;
    float m0r = -1e30f, m1r = -1e30f, l0r = 0.f, l1r = 0.f;

    for (int tt = 0; tt < ntile; tt++) {
        const int kb = (tbase + tt) * 64;
        __syncthreads();
        {
            const int row = tid >> 2;
            const int qd  = (tid & 3) * 16;
            const size_t e = (size_t)(b * S_ + kb + row) * A_ + (tid & 3) * 32;
            const uint4* sh = (const uint4*)(g_khi + e);
            const uint4* sl = (const uint4*)(g_klo + e);
            const int wb = row * AQP + qd;
#pragma unroll
            for (int u = 0; u < 4; u++) {
                *(uint4*)&kh[wb + 4 * u] = sh[u];
                *(uint4*)&kl[wb + 4 * u] = sl[u];
            }
            const int vr = tid >> 1;
            const size_t ev = (size_t)(b * A_ + vr) * S_ + kb + (tid & 1) * 32;
            const uint4* vsh = (const uint4*)(g_vthi + ev);
            const uint4* vsl = (const uint4*)(g_vtlo + ev);
            const int vb = vr * AVP + (tid & 1) * 16;
#pragma unroll
            for (int u = 0; u < 4; u++) {
                *(uint4*)&vh[vb + 4 * u] = vsh[u];
                *(uint4*)&vl[vb + 4 * u] = vsl[u];
            }
        }
        __syncthreads();

        // ---- S = Q K^T (ldmatrix frags, 3-split) ----
        float s[4][4];
#pragma unroll
        for (int nt = 0; nt < 4; nt++)
#pragma unroll
            for (int q = 0; q < 4; q++) s[nt][q] = 0.f;

#pragma unroll
        for (int ks = 0; ks < 8; ks++) {
            unsigned ah[4], al_[4];
            ldm_x4(ah,  qh_a + ks * 32);
            ldm_x4(al_, ql_a + ks * 32);
#pragma unroll
            for (int ntp = 0; ntp < 2; ntp++) {
                unsigned b4h[4], b4l[4];
                ldm_x4(b4h, kh_b + ntp * (16 * AQP * 4) + ks * 32);
                ldm_x4(b4l, kl_b + ntp * (16 * AQP * 4) + ks * 32);
                unsigned bh0[2] = { b4h[0], b4h[2] }, bh1[2] = { b4h[1], b4h[3] };
                unsigned bl0[2] = { b4l[0], b4l[2] }, bl1[2] = { b4l[1], b4l[3] };
                mma16816(s[2*ntp],   ah,  bh0);
                mma16816(s[2*ntp],   ah,  bl0);
                mma16816(s[2*ntp],   al_, bh0);
                mma16816(s[2*ntp+1], ah,  bh1);
                mma16816(s[2*ntp+1], ah,  bl1);
                mma16816(s[2*ntp+1], al_, bh1);
            }
        }

        // causal mask (diagonal tile only)
        if (tbase + tt == qt) {
            const int row0 = q0 + wr * 16 + g;
#pragma unroll
            for (int nt = 0; nt < 4; nt++) {
                const int c0 = kb + wh * 32 + nt * 8 + 2 * t;
                if (c0     > row0)     s[nt][0] = -1e30f;
                if (c0 + 1 > row0)     s[nt][1] = -1e30f;
                if (c0     > row0 + 8) s[nt][2] = -1e30f;
                if (c0 + 1 > row0 + 8) s[nt][3] = -1e30f;
            }
        }

        // ---- warp-local online softmax (no cross-half exchange) ----
        float mx0 = -1e30f, mx1 = -1e30f;
#pragma unroll
        for (int nt = 0; nt < 4; nt++) {
            mx0 = fmaxf(mx0, fmaxf(s[nt][0], s[nt][1]));
            mx1 = fmaxf(mx1, fmaxf(s[nt][2], s[nt][3]));
        }
        mx0 = fmaxf(mx0, __shfl_xor_sync(0xffffffffu, mx0, 1));
        mx0 = fmaxf(mx0, __shfl_xor_sync(0xffffffffu, mx0, 2));
        mx1 = fmaxf(mx1, __shfl_xor_sync(0xffffffffu, mx1, 1));
        mx1 = fmaxf(mx1, __shfl_xor_sync(0xffffffffu, mx1, 2));
        const float mn0 = fmaxf(m0r, mx0);
        const float mn1 = fmaxf(m1r, mx1);
        const float a0 = __expf(m0r - mn0), a1 = __expf(m1r - mn1);
        float sum0 = 0.f, sum1 = 0.f;
#pragma unroll
        for (int nt = 0; nt < 4; nt++) {
            s[nt][0] = __expf(s[nt][0] - mn0);
            s[nt][1] = __expf(s[nt][1] - mn0);
            s[nt][2] = __expf(s[nt][2] - mn1);
            s[nt][3] = __expf(s[nt][3] - mn1);
            sum0 += s[nt][0] + s[nt][1];
            sum1 += s[nt][2] + s[nt][3];
        }
        sum0 += __shfl_xor_sync(0xffffffffu, sum0, 1);
        sum0 += __shfl_xor_sync(0xffffffffu, sum0, 2);
        sum1 += __shfl_xor_sync(0xffffffffu, sum1, 1);
        sum1 += __shfl_xor_sync(0xffffffffu, sum1, 2);
        l0r = l0r * a0 + sum0;  l1r = l1r * a1 + sum1;
        m0r = mn0;  m1r = mn1;

#pragma unroll
        for (int nt = 0; nt < 16; nt++) {
            o[nt][0] *= a0; o[nt][1] *= a0;
            o[nt][2] *= a1; o[nt][3] *= a1;
        }

        // ---- O += P V (P A-frags from S regs; V B-frags via ldmatrix) ----
#pragma unroll
        for (int ks2 = 0; ks2 < 2; ks2++) {
            unsigned pa_h[4], pa_l[4];
            pa_h[0] = pack_bf16_hi(s[2*ks2  ][0], s[2*ks2  ][1]);
            pa_h[1] = pack_bf16_hi(s[2*ks2  ][2], s[2*ks2  ][3]);
            pa_h[2] = pack_bf16_hi(s[2*ks2+1][0], s[2*ks2+1][1]);
            pa_h[3] = pack_bf16_hi(s[2*ks2+1][2], s[2*ks2+1][3]);
            pa_l[0] = pack_bf16_lo(s[2*ks2  ][0], s[2*ks2  ][1]);
            pa_l[1] = pack_bf16_lo(s[2*ks2  ][2], s[2*ks2  ][3]);
            pa_l[2] = pack_bf16_lo(s[2*ks2+1][0], s[2*ks2+1][1]);
            pa_l[3] = pack_bf16_lo(s[2*ks2+1][2], s[2*ks2+1][3]);
            const uint32_t kadv = (uint32_t)((wh * 16 + ks2 * 8) << 2);
#pragma unroll
            for (int ntp2 = 0; ntp2 < 8; ntp2++) {
                unsigned v4h[4], v4l[4];
                const uint32_t va = ntp2 * (16 * AVP * 4) + kadv;
                ldm_x4(v4h, vh_b + va);
                ldm_x4(v4l, vl_b + va);
                unsigned bh0[2] = { v4h[0], v4h[2] }, bh1[2] = { v4h[1], v4h[3] };
                unsigned bl0[2] = { v4l[0], v4l[2] }, bl1[2] = { v4l[1], v4l[3] };
                mma16816(o[2*ntp2],   pa_h, bh0);
                mma16816(o[2*ntp2],   pa_h, bl0);
                mma16816(o[2*ntp2],   pa_l, bh0);
                mma16816(o[2*ntp2+1], pa_h, bh1);
                mma16816(o[2*ntp2+1], pa_h, bl1);
                mma16816(o[2*ntp2+1], pa_l, bh1);
            }
        }
    }

    // ---- epilogue: merge the two independent key-halves ----
    __syncthreads();   // all warps done with kh/kl (obuf aliases them)
    if (wh == 1) {
#pragma unroll
        for (int nt = 0; nt < 16; nt++) {
            const int r0 = wr * 16 + g;
            const int c  = nt * 8 + 2 * t;
            *(float2*)&obuf[r0 * 128 + c]       = make_float2(o[nt][0], o[nt][1]);
            *(float2*)&obuf[(r0 + 8) * 128 + c] = make_float2(o[nt][2], o[nt][3]);
        }
        if (t == 0) {
            red_m1[wr][g]     = m0r;  red_m1[wr][g + 8] = m1r;
            red_l1[wr][g]     = l0r;  red_l1[wr][g + 8] = l1r;
        }
    }
    __syncthreads();
    if (wh == 0) {
        const float mo0 = red_m1[wr][g],     mo1 = red_m1[wr][g + 8];
        const float lo0 = red_l1[wr][g],     lo1 = red_l1[wr][g + 8];
        const float M0 = fmaxf(m0r, mo0),    M1 = fmaxf(m1r, mo1);
        const float w00 = __expf(m0r - M0),  w01 = __expf(mo0 - M0);
        const float w10 = __expf(m1r - M1),  w11 = __expf(mo1 - M1);
        const float L0 = l0r * w00 + lo0 * w01;
        const float L1 = l1r * w10 + lo1 * w11;
#pragma unroll
        for (int nt = 0; nt < 16; nt++) {
            const int r0 = wr * 16 + g;
            const int c  = nt * 8 + 2 * t;
            float2 u0 = *(const float2*)&obuf[r0 * 128 + c];
            float2 u1 = *(const float2*)&obuf[(r0 + 8) * 128 + c];
            o[nt][0] = o[nt][0] * w00 + u0.x * w01;
            o[nt][1] = o[nt][1] * w00 + u0.y * w01;
            o[nt][2] = o[nt][2] * w10 + u1.x * w11;
            o[nt][3] = o[nt][3] * w10 + u1.y * w11;
        }
        if (nch == 1) {
            const float i0 = 1.f / L0, i1 = 1.f / L1;
            const size_t row0 = (size_t)(b * S_ + q0 + wr * 16 + g);
#pragma unroll
            for (int nt = 0; nt < 16; nt++) {
                const int c = nt * 8 + 2 * t;
                *(float2*)&out[row0 * A_ + c] =
                    make_float2(o[nt][0] * i0, o[nt][1] * i0);
                *(float2*)&out[(row0 + 8) * A_ + c] =
                    make_float2(o[nt][2] * i1, o[nt][3] * i1);
            }
        } else {
            const size_t pb = (size_t)(b * 32 + qt) * 4 + chunk;
            float* PO = g_po + pb * 8192;
            const int r0 = wr * 16 + g;
#pragma unroll
            for (int nt = 0; nt < 16; nt++) {
                const int c = nt * 8 + 2 * t;
                *(float2*)&PO[r0 * 128 + c]       = make_float2(o[nt][0], o[nt][1]);
                *(float2*)&PO[(r0 + 8) * 128 + c] = make_float2(o[nt][2], o[nt][3]);
            }
            if (t == 0) {
                g_pml[pb * 64 + r0]     = make_float2(M0, L0);
                g_pml[pb * 64 + r0 + 8] = make_float2(M1, L1);
            }
        }
    }
}

// ---------------------------------------------------------------------------
// Combine kernel: 4x more CTAs (24,4,4); thread = 1 row x 8 cols.
// ---------------------------------------------------------------------------
__global__ __launch_bounds__(256) void attn_combine(float* __restrict__ out)
{
    const int qt  = 8 + blockIdx.x;
    const int b   = blockIdx.y;
    const int nch = (qt >> 3) + 1;
    const int tid = threadIdx.x;
    const int row = tid >> 2;
    const int cq  = blockIdx.z * 32 + (tid & 3) * 8;

    const size_t pb0 = (size_t)(b * 32 + qt) * 4;
    float w[4], lv[4];
    float M = -1e30f;
    for (int c = 0; c < nch; c++) {
        float2 ml = g_pml[(pb0 + c) * 64 + row];
        w[c] = ml.x; lv[c] = ml.y;
        M = fmaxf(M, ml.x);
    }
    float L = 0.f;
    for (int c = 0; c < nch; c++) {
        w[c] = __expf(w[c] - M);
        L += w[c] * lv[c];
    }
    const float invL = 1.f / L;

    const size_t ob = (size_t)(b * S_ + qt * 64 + row) * A_ + cq;
#pragma unroll
    for (int j = 0; j < 8; j += 4) {
        float4 acc = make_float4(0.f, 0.f, 0.f, 0.f);
        for (int c = 0; c < nch; c++) {
            const float4 v = *(const float4*)
                &g_po[(pb0 + c) * 8192 + row * 128 + cq + j];
            acc.x += w[c] * v.x; acc.y += w[c] * v.y;
            acc.z += w[c] * v.z; acc.w += w[c] * v.w;
        }
        *(float4*)&out[ob + j] = make_float4(acc.x * invL, acc.y * invL,
                                             acc.z * invL, acc.w * invL);
    }
}

// ---------------------------------------------------------------------------
extern "C" void kernel_launch(void* const* d_in, const int* in_sizes, int n_in,
                              void* d_out, int out_size)
{
    const float* x  = (const float*)d_in[0];
    const float* Wk = (const float*)d_in[1];
    const float* Wq = (const float*)d_in[2];
    const float* Wv = (const float*)d_in[3];
    float* out = (float*)d_out;

    cudaFuncSetAttribute(proj_mma2,
                         cudaFuncAttributeMaxDynamicSharedMemorySize,
                         PROJ_SMEM);
    cudaFuncSetAttribute(attn_chunk,
                         cudaFuncAttributeMaxDynamicSharedMemorySize,
                         ATTN_SMEM);

    split_xw<<<4096, 256>>>(x, Wk, Wq, Wv);
    proj_mma2<<<dim3(64, 3), 256, PROJ_SMEM>>>();
    attn_chunk<<<320, 256, ATTN_SMEM>>>(out);
    attn_combine<<<dim3(24, 4, 4), 256>>>(out);
}

// round 15
// speedup vs baseline: 1.0472x; 1.0472x over previous
#include <cuda_runtime.h>
#include <cuda_bf16.h>
#include <cstdint>

#define B_ 4
#define S_ 2048
#define E_ 1024
#define A_ 128
#define M_ (B_*S_)   // 8192

// ---- mma.sync bf16 + cp.async (base ISA, compiles for compute_103) ----
__device__ __forceinline__ void mma16816(float* d, const unsigned* a, const unsigned* b) {
    asm volatile(
        "mma.sync.aligned.m16n8k16.row.col.f32.bf16.bf16.f32 "
        "{%0,%1,%2,%3}, {%4,%5,%6,%7}, {%8,%9}, {%0,%1,%2,%3};"
        : "+f"(d[0]), "+f"(d[1]), "+f"(d[2]), "+f"(d[3])
        : "r"(a[0]), "r"(a[1]), "r"(a[2]), "r"(a[3]), "r"(b[0]), "r"(b[1]));
}
__device__ __forceinline__ uint32_t smem_u32(const void* p) {
    uint32_t a;
    asm("{ .reg .u64 t; cvta.to.shared.u64 t, %1; cvt.u32.u64 %0, t; }"
        : "=r"(a) : "l"(p));
    return a;
}
__device__ __forceinline__ void cp16(uint32_t dst, const void* src) {
    asm volatile("cp.async.cg.shared.global [%0], [%1], 16;"
                 :: "r"(dst), "l"(src));
}
#define CP_COMMIT() asm volatile("cp.async.commit_group;" ::: "memory")
#define CP_WAIT(n)  asm volatile("cp.async.wait_group %0;" :: "n"(n) : "memory")

__device__ __forceinline__ unsigned pack_bf16_hi(float a, float b) {
    __nv_bfloat162 h = __floats2bfloat162_rn(a, b);
    return *reinterpret_cast<unsigned*>(&h);
}
__device__ __forceinline__ unsigned pack_bf16_lo(float a, float b) {
    float ra = a - __bfloat162float(__float2bfloat16(a));
    float rb = b - __bfloat162float(__float2bfloat16(b));
    __nv_bfloat162 h = __floats2bfloat162_rn(ra, rb);
    return *reinterpret_cast<unsigned*>(&h);
}

// scratch (device globals: no allocation allowed)
__device__ __nv_bfloat16 g_xhi[M_*E_], g_xlo[M_*E_];
__device__ __nv_bfloat16 g_whi[3*A_*E_], g_wlo[3*A_*E_];
__device__ __nv_bfloat16 g_qhi[M_*A_], g_qlo[M_*A_];
__device__ __nv_bfloat16 g_khi[M_*A_], g_klo[M_*A_];
__device__ __nv_bfloat16 g_vthi[M_*A_], g_vtlo[M_*A_];
__device__ float  g_po [4*32*4*64*128];
__device__ float2 g_pml[4*32*4*64];

// ---------------------------------------------------------------------------
// split_xw (R12-proven, unchanged)
// ---------------------------------------------------------------------------
__global__ __launch_bounds__(256) void split_xw(
    const float* __restrict__ x,
    const float* __restrict__ Wk,
    const float* __restrict__ Wq,
    const float* __restrict__ Wv)
{
    const int NX  = M_ * E_ / 4;
    const int NW1 = A_ * E_ / 4;
    const int NT  = NX + 3 * NW1;
    for (int i = blockIdx.x * blockDim.x + threadIdx.x; i < NT;
         i += gridDim.x * blockDim.x) {
        const float4* src;
        __nv_bfloat16 *dh, *dl;
        int idx;
        if (i < NX) {
            src = (const float4*)x; idx = i; dh = g_xhi; dl = g_xlo;
        } else {
            int j = i - NX; int w = j / NW1; idx = j - w * NW1;
            src = (const float4*)(w == 0 ? Wk : (w == 1 ? Wq : Wv));
            dh = g_whi + (size_t)w * A_ * E_;
            dl = g_wlo + (size_t)w * A_ * E_;
        }
        float4 v = src[idx];
        uint2 h, l;
        h.x = pack_bf16_hi(v.x, v.y); h.y = pack_bf16_hi(v.z, v.w);
        l.x = pack_bf16_lo(v.x, v.y); l.y = pack_bf16_lo(v.z, v.w);
        *(uint2*)(dh + (size_t)idx * 4) = h;
        *(uint2*)(dl + (size_t)idx * 4) = l;
    }
}

// ---------------------------------------------------------------------------
// Projection (R13-proven scalar-LDS frags; staging via cp.async).
// ---------------------------------------------------------------------------
#define PP 36
#define TILE_W (128 * PP)
#define DP 132
#define PROJ_SMEM (4 * TILE_W * 4)

__global__ __launch_bounds__(256, 2) void proj_mma2()
{
    extern __shared__ unsigned smu[];
    unsigned* x_hi = smu;
    unsigned* x_lo = smu + TILE_W;
    unsigned* w_hi = smu + 2 * TILE_W;
    unsigned* w_lo = smu + 3 * TILE_W;

    const int which = blockIdx.y;
    const int m0   = blockIdx.x * 128;
    const int tid  = threadIdx.x;
    const int wid  = tid >> 5;
    const int lane = tid & 31;
    const int wr   = wid >> 1;
    const int wc   = wid & 1;
    const int g    = lane >> 2;
    const int t    = lane & 3;

    const __nv_bfloat16* wbh = g_whi + (size_t)which * A_ * E_;
    const __nv_bfloat16* wbl = g_wlo + (size_t)which * A_ * E_;

    float acc[2][8][4];
#pragma unroll
    for (int rt = 0; rt < 2; rt++)
#pragma unroll
        for (int nt = 0; nt < 8; nt++)
#pragma unroll
            for (int q = 0; q < 4; q++) acc[rt][nt][q] = 0.f;

    const int row  = tid >> 1;
    const int half = tid & 1;
    const uint32_t sxh = smem_u32(x_hi) + ((row * PP + half * 16) << 2);
    const uint32_t sxl = smem_u32(x_lo) + ((row * PP + half * 16) << 2);
    const uint32_t swh = smem_u32(w_hi) + ((row * PP + half * 16) << 2);
    const uint32_t swl = smem_u32(w_lo) + ((row * PP + half * 16) << 2);

    for (int c = 0; c < 16; c++) {
        __syncthreads();   // prev compute done reading tiles
        {
            const size_t xe = (size_t)(m0 + row) * E_ + c * 64 + half * 32;
            const size_t we = (size_t)row * E_ + c * 64 + half * 32;
            const char* pxh = (const char*)(g_xhi + xe);
            const char* pxl = (const char*)(g_xlo + xe);
            const char* pwh = (const char*)(wbh + we);
            const char* pwl = (const char*)(wbl + we);
#pragma unroll
            for (int u = 0; u < 4; u++) {
                cp16(sxh + 16 * u, pxh + 16 * u);
                cp16(sxl + 16 * u, pxl + 16 * u);
                cp16(swh + 16 * u, pwh + 16 * u);
                cp16(swl + 16 * u, pwl + 16 * u);
            }
            CP_COMMIT();
            CP_WAIT(0);
        }
        __syncthreads();

#pragma unroll
        for (int ks = 0; ks < 4; ks++) {
            const int kw = ks * 8;
            unsigned ah[2][4], al[2][4];
#pragma unroll
            for (int rt = 0; rt < 2; rt++) {
                const int rb = wr * 32 + rt * 16;
                const int r0 = (rb + g) * PP + kw + t;
                const int r1 = (rb + g + 8) * PP + kw + t;
                ah[rt][0] = x_hi[r0];     ah[rt][1] = x_hi[r1];
                ah[rt][2] = x_hi[r0 + 4]; ah[rt][3] = x_hi[r1 + 4];
                al[rt][0] = x_lo[r0];     al[rt][1] = x_lo[r1];
                al[rt][2] = x_lo[r0 + 4]; al[rt][3] = x_lo[r1 + 4];
            }
#pragma unroll
            for (int nt = 0; nt < 8; nt++) {
                const int nb = wc * 64 + nt * 8;
                const int b0 = (nb + g) * PP + kw + t;
                unsigned bh[2] = { w_hi[b0], w_hi[b0 + 4] };
                unsigned bl[2] = { w_lo[b0], w_lo[b0 + 4] };
#pragma unroll
                for (int rt = 0; rt < 2; rt++) {
                    mma16816(acc[rt][nt], ah[rt], bh);
                    mma16816(acc[rt][nt], ah[rt], bl);
                    mma16816(acc[rt][nt], al[rt], bh);
                }
            }
        }
    }

    __syncthreads();
    float* Dsm = (float*)smu;
#pragma unroll
    for (int rt = 0; rt < 2; rt++) {
#pragma unroll
        for (int nt = 0; nt < 8; nt++) {
            const int rowA = wr * 32 + rt * 16 + g;
            const int col  = wc * 64 + nt * 8 + 2 * t;
            *(float2*)&Dsm[rowA * DP + col] =
                make_float2(acc[rt][nt][0], acc[rt][nt][1]);
            *(float2*)&Dsm[(rowA + 8) * DP + col] =
                make_float2(acc[rt][nt][2], acc[rt][nt][3]);
        }
    }
    __syncthreads();

    const int bb = m0 >> 11;
    const int s0 = m0 & (S_ - 1);
    if (which == 2) {
        const int n  = tid >> 1;
        const int r0 = (tid & 1) * 64;
        const size_t base = ((size_t)(bb * A_ + n)) * S_ + s0 + r0;
#pragma unroll
        for (int u = 0; u < 8; u++) {
            float f[8];
#pragma unroll
            for (int j = 0; j < 8; j++) f[j] = Dsm[(r0 + 8 * u + j) * DP + n];
            uint4 h = make_uint4(pack_bf16_hi(f[0], f[1]), pack_bf16_hi(f[2], f[3]),
                                 pack_bf16_hi(f[4], f[5]), pack_bf16_hi(f[6], f[7]));
            uint4 l = make_uint4(pack_bf16_lo(f[0], f[1]), pack_bf16_lo(f[2], f[3]),
                                 pack_bf16_lo(f[4], f[5]), pack_bf16_lo(f[6], f[7]));
            *(uint4*)(g_vthi + base + 8 * u) = h;
            *(uint4*)(g_vtlo + base + 8 * u) = l;
        }
    } else {
        const float sc = (which == 1) ? 0.08838834764831843f : 1.0f;
        __nv_bfloat16* dsth = (which == 1) ? g_qhi : g_khi;
        __nv_bfloat16* dstl = (which == 1) ? g_qlo : g_klo;
        const int rr = tid >> 1;
        const int cb = (tid & 1) * 64;
        const float* sp = &Dsm[rr * DP + cb];
        const size_t base = (size_t)(m0 + rr) * A_ + cb;
#pragma unroll
        for (int u = 0; u < 8; u++) {
            float f[8];
#pragma unroll
            for (int j = 0; j < 8; j++) f[j] = sp[8 * u + j] * sc;
            uint4 h = make_uint4(pack_bf16_hi(f[0], f[1]), pack_bf16_hi(f[2], f[3]),
                                 pack_bf16_hi(f[4], f[5]), pack_bf16_hi(f[6], f[7]));
            uint4 l = make_uint4(pack_bf16_lo(f[0], f[1]), pack_bf16_lo(f[2], f[3]),
                                 pack_bf16_lo(f[4], f[5]), pack_bf16_lo(f[6], f[7]));
            *(uint4*)(dsth + base + 8 * u) = h;
            *(uint4*)(dstl + base + 8 * u) = l;
        }
    }
}

// ---------------------------------------------------------------------------
// Split-K flash attention chunk kernel (R13-proven compute structure)
// + DOUBLE-BUFFERED K/V staging via cp.async: tile t+1 streams in during
// the full compute of tile t (1 CTA/SM -> intra-CTA overlap is the only way).
// smem: Q (2*QW) + 2x K (2*QW each) + 2x V (2*VW each) = 178176 B.
// ---------------------------------------------------------------------------
#define AQP 68
#define AVP 36
#define QW (64 * AQP)
#define VW (128 * AVP)
#define ATTN_SMEM ((6 * QW + 4 * VW) * 4)   // 178176 B

__global__ __launch_bounds__(256) void attn_chunk(float* __restrict__ out)
{
    extern __shared__ unsigned smw[];
    unsigned* qh = smw;
    unsigned* ql = qh + QW;
    unsigned* kbuf = smw + 2 * QW;          // [buf][kh|kl], stride 2*QW
    unsigned* vbuf = smw + 6 * QW;          // [buf][vh|vl], stride 2*VW
    float* obuf = (float*)kbuf;             // epilogue reuse (34816B >= 32KB)
    __shared__ float red_m[2][4][16];
    __shared__ float red_s[2][4][16];

    int cid = blockIdx.x;
    const int b = cid / 80;  cid -= b * 80;
    int qt, chunk;
    if (cid < 8)       { qt = cid;                    chunk = 0; }
    else if (cid < 24) { qt = 8  + ((cid - 8) >> 1);  chunk = (cid - 8) & 1; }
    else if (cid < 48) { qt = 16 + (cid - 24) / 3;    chunk = (cid - 24) % 3; }
    else               { qt = 24 + ((cid - 48) >> 2); chunk = (cid - 48) & 3; }
    const int nch   = (qt >> 3) + 1;
    const int tbase = chunk * 8;
    int ntile = qt + 1 - tbase;
    if (ntile > 8) ntile = 8;
    const int q0 = qt * 64;

    const int tid  = threadIdx.x;
    const int wid  = tid >> 5;
    const int lane = tid & 31;
    const int wr   = wid >> 1;      // row group (16 rows)
    const int wh   = wid & 1;       // key half (32 keys)
    const int g    = lane >> 2;
    const int t    = lane & 3;

    // per-thread staging coordinates
    const int srow = tid >> 2;
    const int sqd  = (tid & 3) * 16;                  // word offset
    const uint32_t k_s0 = smem_u32(kbuf) + ((srow * AQP + sqd) << 2);
    const int vrow = tid >> 1;
    const uint32_t v_s0 = smem_u32(vbuf) + ((vrow * AVP + (tid & 1) * 16) << 2);

    // stage Q tile (plain loads)
    {
        const size_t e = (size_t)(b * S_ + q0 + srow) * A_ + (tid & 3) * 32;
        const uint4* sh = (const uint4*)(g_qhi + e);
        const uint4* sl = (const uint4*)(g_qlo + e);
        const int wb = srow * AQP + sqd;
#pragma unroll
        for (int u = 0; u < 4; u++) {
            *(uint4*)&qh[wb + 4 * u] = sh[u];
            *(uint4*)&ql[wb + 4 * u] = sl[u];
        }
    }

    // prefetch tile 0 into buffer 0
    {
        const int kb0 = tbase * 64;
        const size_t e  = (size_t)(b * S_ + kb0 + srow) * A_ + (tid & 3) * 32;
        const size_t ev = (size_t)(b * A_ + vrow) * S_ + kb0 + (tid & 1) * 32;
        const char* pkh = (const char*)(g_khi + e);
        const char* pkl = (const char*)(g_klo + e);
        const char* pvh = (const char*)(g_vthi + ev);
        const char* pvl = (const char*)(g_vtlo + ev);
#pragma unroll
        for (int u = 0; u < 4; u++) {
            cp16(k_s0 + 16 * u,               pkh + 16 * u);
            cp16(k_s0 + (QW << 2) + 16 * u,   pkl + 16 * u);
            cp16(v_s0 + 16 * u,               pvh + 16 * u);
            cp16(v_s0 + (VW << 2) + 16 * u,   pvl + 16 * u);
        }
        CP_COMMIT();
    }

    float o[16][4];
#pragma unroll
    for (int nt = 0; nt < 16; nt++)
#pragma unroll
        for (int q = 0; q < 4; q++) o[nt][q] = 0.f;
    float m0r = -1e30f, m1r = -1e30f, l0r = 0.f, l1r = 0.f;

    for (int tt = 0; tt < ntile; tt++) {
        const int kb = (tbase + tt) * 64;
        const int buf = tt & 1;
        if (tt > 0) __syncthreads();   // all warps done with compute tt-1

        const bool hasnext = (tt + 1 < ntile);
        if (hasnext) {
            const int kbn = (tbase + tt + 1) * 64;
            const int nb = (tt + 1) & 1;
            const size_t e  = (size_t)(b * S_ + kbn + srow) * A_ + (tid & 3) * 32;
            const size_t ev = (size_t)(b * A_ + vrow) * S_ + kbn + (tid & 1) * 32;
            const char* pkh = (const char*)(g_khi + e);
            const char* pkl = (const char*)(g_klo + e);
            const char* pvh = (const char*)(g_vthi + ev);
            const char* pvl = (const char*)(g_vtlo + ev);
            const uint32_t ks = k_s0 + nb * (2 * QW << 2);
            const uint32_t vs = v_s0 + nb * (2 * VW << 2);
#pragma unroll
            for (int u = 0; u < 4; u++) {
                cp16(ks + 16 * u,             pkh + 16 * u);
                cp16(ks + (QW << 2) + 16 * u, pkl + 16 * u);
                cp16(vs + 16 * u,             pvh + 16 * u);
                cp16(vs + (VW << 2) + 16 * u, pvl + 16 * u);
            }
            CP_COMMIT();
            CP_WAIT(1);    // tile tt complete (its group is the older one)
        } else {
            CP_WAIT(0);
        }
        __syncthreads();

        const unsigned* kh = kbuf + buf * (2 * QW);
        const unsigned* kl = kh + QW;
        const unsigned* vh = vbuf + buf * (2 * VW);
        const unsigned* vl = vh + VW;

        // ---- S = Q K^T over this warp's 16 rows x 32 keys (3-split) ----
        float s[4][4];
#pragma unroll
        for (int nt = 0; nt < 4; nt++)
#pragma unroll
            for (int q = 0; q < 4; q++) s[nt][q] = 0.f;

#pragma unroll
        for (int ks = 0; ks < 8; ks++) {
            const int r0 = (wr * 16 + g) * AQP + ks * 8 + t;
            const int r1 = r0 + 8 * AQP;
            unsigned ah[4]  = { qh[r0], qh[r1], qh[r0 + 4], qh[r1 + 4] };
            unsigned al_[4] = { ql[r0], ql[r1], ql[r0 + 4], ql[r1 + 4] };
#pragma unroll
            for (int nt = 0; nt < 4; nt++) {
                const int bw = (wh * 32 + nt * 8 + g) * AQP + ks * 8 + t;
                unsigned bh[2] = { kh[bw], kh[bw + 4] };
                unsigned bl[2] = { kl[bw], kl[bw + 4] };
                mma16816(s[nt], ah, bh);
                mma16816(s[nt], ah, bl);
                mma16816(s[nt], al_, bh);
            }
        }

        // causal mask (diagonal tile only)
        if (tbase + tt == qt) {
            const int row0 = q0 + wr * 16 + g;
#pragma unroll
            for (int nt = 0; nt < 4; nt++) {
                const int c0 = kb + wh * 32 + nt * 8 + 2 * t;
                if (c0     > row0)     s[nt][0] = -1e30f;
                if (c0 + 1 > row0)     s[nt][1] = -1e30f;
                if (c0     > row0 + 8) s[nt][2] = -1e30f;
                if (c0 + 1 > row0 + 8) s[nt][3] = -1e30f;
            }
        }

        // ---- online softmax with cross-half combine (R13-proven) ----
        float mx0 = -1e30f, mx1 = -1e30f;
#pragma unroll
        for (int nt = 0; nt < 4; nt++) {
            mx0 = fmaxf(mx0, fmaxf(s[nt][0], s[nt][1]));
            mx1 = fmaxf(mx1, fmaxf(s[nt][2], s[nt][3]));
        }
        mx0 = fmaxf(mx0, __shfl_xor_sync(0xffffffffu, mx0, 1));
        mx0 = fmaxf(mx0, __shfl_xor_sync(0xffffffffu, mx0, 2));
        mx1 = fmaxf(mx1, __shfl_xor_sync(0xffffffffu, mx1, 1));
        mx1 = fmaxf(mx1, __shfl_xor_sync(0xffffffffu, mx1, 2));
        if (t == 0) {
            red_m[wh][wr][g]     = mx0;
            red_m[wh][wr][g + 8] = mx1;
        }
        __syncthreads();
        const float mn0 = fmaxf(m0r, fmaxf(mx0, red_m[wh ^ 1][wr][g]));
        const float mn1 = fmaxf(m1r, fmaxf(mx1, red_m[wh ^ 1][wr][g + 8]));
        const float a0 = __expf(m0r - mn0), a1 = __expf(m1r - mn1);
        float sum0 = 0.f, sum1 = 0.f;
#pragma unroll
        for (int nt = 0; nt < 4; nt++) {
            s[nt][0] = __expf(s[nt][0] - mn0);
            s[nt][1] = __expf(s[nt][1] - mn0);
            s[nt][2] = __expf(s[nt][2] - mn1);
            s[nt][3] = __expf(s[nt][3] - mn1);
            sum0 += s[nt][0] + s[nt][1];
            sum1 += s[nt][2] + s[nt][3];
        }
        sum0 += __shfl_xor_sync(0xffffffffu, sum0, 1);
        sum0 += __shfl_xor_sync(0xffffffffu, sum0, 2);
        sum1 += __shfl_xor_sync(0xffffffffu, sum1, 1);
        sum1 += __shfl_xor_sync(0xffffffffu, sum1, 2);
        if (t == 0) {
            red_s[wh][wr][g]     = sum0;
            red_s[wh][wr][g + 8] = sum1;
        }
#pragma unroll
        for (int nt = 0; nt < 16; nt++) {
            o[nt][0] *= a0; o[nt][1] *= a0;
            o[nt][2] *= a1; o[nt][3] *= a1;
        }
        __syncthreads();
        l0r = l0r * a0 + sum0 + red_s[wh ^ 1][wr][g];
        l1r = l1r * a1 + sum1 + red_s[wh ^ 1][wr][g + 8];
        m0r = mn0;  m1r = mn1;

        // ---- O += P V over this warp's 32 keys ----
#pragma unroll
        for (int ks2 = 0; ks2 < 2; ks2++) {
            unsigned pa_h[4], pa_l[4];
            pa_h[0] = pack_bf16_hi(s[2*ks2  ][0], s[2*ks2  ][1]);
            pa_h[1] = pack_bf16_hi(s[2*ks2  ][2], s[2*ks2  ][3]);
            pa_h[2] = pack_bf16_hi(s[2*ks2+1][0], s[2*ks2+1][1]);
            pa_h[3] = pack_bf16_hi(s[2*ks2+1][2], s[2*ks2+1][3]);
            pa_l[0] = pack_bf16_lo(s[2*ks2  ][0], s[2*ks2  ][1]);
            pa_l[1] = pack_bf16_lo(s[2*ks2  ][2], s[2*ks2  ][3]);
            pa_l[2] = pack_bf16_lo(s[2*ks2+1][0], s[2*ks2+1][1]);
            pa_l[3] = pack_bf16_lo(s[2*ks2+1][2], s[2*ks2+1][3]);
#pragma unroll
            for (int nt2 = 0; nt2 < 16; nt2++) {
                const int bw = (nt2 * 8 + g) * AVP + wh * 16 + ks2 * 8 + t;
                unsigned bh[2] = { vh[bw], vh[bw + 4] };
                unsigned bl[2] = { vl[bw], vl[bw + 4] };
                mma16816(o[nt2], pa_h, bh);
                mma16816(o[nt2], pa_h, bl);
                mma16816(o[nt2], pa_l, bh);
            }
        }
    }

    // ---- pair-sum across key halves, then output (R13-proven) ----
    __syncthreads();
    if (wh == 1) {
#pragma unroll
        for (int nt = 0; nt < 16; nt++) {
            const int r0 = wr * 16 + g;
            const int c  = nt * 8 + 2 * t;
            *(float2*)&obuf[r0 * 128 + c]       = make_float2(o[nt][0], o[nt][1]);
            *(float2*)&obuf[(r0 + 8) * 128 + c] = make_float2(o[nt][2], o[nt][3]);
        }
    }
    __syncthreads();
    if (wh == 0) {
#pragma unroll
        for (int nt = 0; nt < 16; nt++) {
            const int r0 = wr * 16 + g;
            const int c  = nt * 8 + 2 * t;
            float2 u0 = *(const float2*)&obuf[r0 * 128 + c];
            float2 u1 = *(const float2*)&obuf[(r0 + 8) * 128 + c];
            o[nt][0] += u0.x; o[nt][1] += u0.y;
            o[nt][2] += u1.x; o[nt][3] += u1.y;
        }
        if (nch == 1) {
            const float i0 = 1.f / l0r, i1 = 1.f / l1r;
            const size_t row0 = (size_t)(b * S_ + q0 + wr * 16 + g);
#pragma unroll
            for (int nt = 0; nt < 16; nt++) {
                const int c = nt * 8 + 2 * t;
                *(float2*)&out[row0 * A_ + c] =
                    make_float2(o[nt][0] * i0, o[nt][1] * i0);
                *(float2*)&out[(row0 + 8) * A_ + c] =
                    make_float2(o[nt][2] * i1, o[nt][3] * i1);
            }
        } else {
            const size_t pb = (size_t)(b * 32 + qt) * 4 + chunk;
            float* PO = g_po + pb * 8192;
            const int r0 = wr * 16 + g;
#pragma unroll
            for (int nt = 0; nt < 16; nt++) {
                const int c = nt * 8 + 2 * t;
                *(float2*)&PO[r0 * 128 + c]       = make_float2(o[nt][0], o[nt][1]);
                *(float2*)&PO[(r0 + 8) * 128 + c] = make_float2(o[nt][2], o[nt][3]);
            }
            if (t == 0) {
                g_pml[pb * 64 + r0]     = make_float2(m0r, l0r);
                g_pml[pb * 64 + r0 + 8] = make_float2(m1r, l1r);
            }
        }
    }
}

// ---------------------------------------------------------------------------
// Combine kernel (R14-measured win: 384 CTAs, 8 cols/thread)
// ---------------------------------------------------------------------------
__global__ __launch_bounds__(256) void attn_combine(float* __restrict__ out)
{
    const int qt  = 8 + blockIdx.x;
    const int b   = blockIdx.y;
    const int nch = (qt >> 3) + 1;
    const int tid = threadIdx.x;
    const int row = tid >> 2;
    const int cq  = blockIdx.z * 32 + (tid & 3) * 8;

    const size_t pb0 = (size_t)(b * 32 + qt) * 4;
    float w[4], lv[4];
    float M = -1e30f;
    for (int c = 0; c < nch; c++) {
        float2 ml = g_pml[(pb0 + c) * 64 + row];
        w[c] = ml.x; lv[c] = ml.y;
        M = fmaxf(M, ml.x);
    }
    float L = 0.f;
    for (int c = 0; c < nch; c++) {
        w[c] = __expf(w[c] - M);
        L += w[c] * lv[c];
    }
    const float invL = 1.f / L;

    const size_t ob = (size_t)(b * S_ + qt * 64 + row) * A_ + cq;
#pragma unroll
    for (int j = 0; j < 8; j += 4) {
        float4 acc = make_float4(0.f, 0.f, 0.f, 0.f);
        for (int c = 0; c < nch; c++) {
            const float4 v = *(const float4*)
                &g_po[(pb0 + c) * 8192 + row * 128 + cq + j];
            acc.x += w[c] * v.x; acc.y += w[c] * v.y;
            acc.z += w[c] * v.z; acc.w += w[c] * v.w;
        }
        *(float4*)&out[ob + j] = make_float4(acc.x * invL, acc.y * invL,
                                             acc.z * invL, acc.w * invL);
    }
}

// ---------------------------------------------------------------------------
extern "C" void kernel_launch(void* const* d_in, const int* in_sizes, int n_in,
                              void* d_out, int out_size)
{
    const float* x  = (const float*)d_in[0];
    const float* Wk = (const float*)d_in[1];
    const float* Wq = (const float*)d_in[2];
    const float* Wv = (const float*)d_in[3];
    float* out = (float*)d_out;

    cudaFuncSetAttribute(proj_mma2,
                         cudaFuncAttributeMaxDynamicSharedMemorySize,
                         PROJ_SMEM);
    cudaFuncSetAttribute(attn_chunk,
                         cudaFuncAttributeMaxDynamicSharedMemorySize,
                         ATTN_SMEM);

    split_xw<<<4096, 256>>>(x, Wk, Wq, Wv);
    proj_mma2<<<dim3(64, 3), 256, PROJ_SMEM>>>();
    attn_chunk<<<320, 256, ATTN_SMEM>>>(out);
    attn_combine<<<dim3(24, 4, 4), 256>>>(out);
}